// round 4
// baseline (speedup 1.0000x reference)
#include <cuda_runtime.h>

// TokenMixer: out = x_pos * (1 - sigmoid( <x_pre,x_pos> / (||x_pre||*||x_pos||) ))
// Shapes: [N=4096, B=16, C=512] f32. One warp per row.
// R4: occupancy-first. Don't keep x_pos live across the reduce tail —
// consume a/b immediately in the accumulate loop, then RE-LOAD x_pos for
// the scaled store (second read is an L2 hit: same 2KB row, ~100s of cycles
// later; DRAM traffic unchanged). __launch_bounds__(256,8) pins regs<=32
// -> 64 warps/SM theoretical (R1 was 35 regs / ~51 warps).

#define ROWS_TOTAL (4096 * 16)
#define F4_PER_ROW 128   // 512 floats / 4
#define WARPS_PER_BLOCK 8

__global__ __launch_bounds__(WARPS_PER_BLOCK * 32, 8)
void token_mixer_kernel(const float4* __restrict__ pre,
                        const float4* __restrict__ pos,
                        float4* __restrict__ out) {
    const int warp_id = threadIdx.x >> 5;
    const int lane    = threadIdx.x & 31;
    const int row     = blockIdx.x * WARPS_PER_BLOCK + warp_id;  // exact cover

    const size_t base = (size_t)row * F4_PER_ROW;
    const float4* __restrict__ p = pre + base + lane;
    const float4* __restrict__ q = pos + base + lane;

    float dot = 0.f, sa = 0.f, sb = 0.f;

    // Accumulate; a and b die inside each iteration (low register pressure,
    // ptxas free to software-pipeline loads within the 32-reg budget).
    #pragma unroll
    for (int i = 0; i < 4; i++) {
        const float4 a = p[i * 32];
        const float4 b = q[i * 32];
        dot += a.x*b.x + a.y*b.y + a.z*b.z + a.w*b.w;
        sa  += a.x*a.x + a.y*a.y + a.z*a.z + a.w*a.w;
        sb  += b.x*b.x + b.y*b.y + b.z*b.z + b.w*b.w;
    }

    // Warp tree-reduce the three scalars.
    #pragma unroll
    for (int off = 16; off > 0; off >>= 1) {
        dot += __shfl_xor_sync(0xffffffffu, dot, off);
        sa  += __shfl_xor_sync(0xffffffffu, sa,  off);
        sb  += __shfl_xor_sync(0xffffffffu, sb,  off);
    }

    const float na = fmaxf(sqrtf(sa), 1e-12f);
    const float nb = fmaxf(sqrtf(sb), 1e-12f);
    const float d  = dot / (na * nb);
    // 1 - sigmoid(d) = 1 / (1 + exp(d))
    const float w  = 1.0f / (1.0f + __expf(d));

    // Re-load x_pos (L2 hit), scale, store.
    float4* __restrict__ o = out + base + lane;
    #pragma unroll
    for (int i = 0; i < 4; i++) {
        float4 b = q[i * 32];
        b.x *= w; b.y *= w; b.z *= w; b.w *= w;
        o[i * 32] = b;
    }
}

extern "C" void kernel_launch(void* const* d_in, const int* in_sizes, int n_in,
                              void* d_out, int out_size) {
    const float4* pre = (const float4*)d_in[0];
    const float4* pos = (const float4*)d_in[1];
    float4* out = (float4*)d_out;
    const int blocks = ROWS_TOTAL / WARPS_PER_BLOCK;  // 8192
    token_mixer_kernel<<<blocks, WARPS_PER_BLOCK * 32>>>(pre, pos, out);
}